// round 14
// baseline (speedup 1.0000x reference)
#include <cuda_runtime.h>
#include <math.h>

#define BB 16
#define TT 800
#define LL 160
#define DD 80
#define KK2 (2*DD)
#define HALF_LOG2PI 0.9189385332046727f
#define LOG2E_F 1.4426950408889634f
#define LN2_F   0.6931471805599453f
#define NEG_INF2 (-1.4426950408889634e20f)   // -1e20 in log2 units
#define MTILES 13                            // ceil(800/64)

__device__ __align__(16) float g_W[BB * KK2 * LL];   // [b][k][l]
__device__ __align__(16) float g_C[BB * LL];
__device__ unsigned g_ready[BB * MTILES];            // 3 n-blocks arrive per tile

// ---------------------------------------------------------------------------
__device__ __forceinline__ float tanha_(float x) {
    float r; asm("tanh.approx.f32 %0, %1;" : "=f"(r) : "f"(x)); return r;
}
__device__ __forceinline__ float ex2f_(float x) {
    float r; asm("ex2.approx.ftz.f32 %0, %1;" : "=f"(r) : "f"(x)); return r;
}
__device__ __forceinline__ float lg2f_(float x) {
    float r; asm("lg2.approx.ftz.f32 %0, %1;" : "=f"(r) : "f"(x)); return r;
}
__device__ __forceinline__ unsigned ld_acq_(const unsigned* p) {
    unsigned v;
    asm volatile("ld.acquire.gpu.u32 %0, [%1];" : "=r"(v) : "l"(p));
    return v;
}

// ---------------------------------------------------------------------------
// K0: param transform + zero loss + zero readiness flags (unchanged).
// ---------------------------------------------------------------------------
__global__ void param_kernel(const float* __restrict__ mu_sigma,
                             float* __restrict__ loss) {
    if (blockIdx.x == 0) {
        if (threadIdx.x == 0) *loss = 0.f;
        if (threadIdx.x < BB * MTILES) g_ready[threadIdx.x] = 0u;
    }

    int wl   = (blockIdx.x * blockDim.x + threadIdx.x) >> 5;
    int lane = threadIdx.x & 31;
    if (wl >= BB * LL) return;
    int b = wl / LL, l = wl % LL;
    const float* ms = mu_sigma + (size_t)(b * LL + l) * KK2;

    float qmu = 0.f, sl = 0.f;
    for (int d = lane; d < DD; d += 32) {
        float mu = 2.f + 2.f * tanha_(0.5f * ms[d]);        // 4*sigmoid(x)
        float ls = 4.f * tanha_(ms[DD + d]);                // 4*tanh(x)
        float iv = ex2f_(-2.f * LOG2E_F * ls);              // exp(-2*ls)
        g_W[((size_t)b * KK2 + d)      * LL + l] = -0.5f * iv;
        g_W[((size_t)b * KK2 + DD + d) * LL + l] = mu * iv;
        qmu += mu * mu * iv;
        sl  += ls;
    }
#pragma unroll
    for (int o = 16; o; o >>= 1) {
        qmu += __shfl_xor_sync(0xffffffffu, qmu, o);
        sl  += __shfl_xor_sync(0xffffffffu, sl, o);
    }
    if (lane == 0)
        g_C[b * LL + l] = -0.5f * qmu - 0.5f * sl - (float)DD * HALF_LOG2PI;
}

// ---------------------------------------------------------------------------
__device__ __forceinline__ float lse2_(float a, float p, float lpv) {
    float m = fmaxf(a, p);
    float d = fminf(a, p) - m;             // <= 0
    float s = lg2f_(1.f + ex2f_(d));
    return fmaf(lpv, LOG2E_F, m) + s;
}

#define SCAN_BAR() asm volatile("bar.sync 1, 64;" ::: "memory")

// Poll (lane 0) until tiles 0..MT of batch b are ready; cumulative cursor.
#define POLL_TILES(MT)                                                         \
    {                                                                          \
        int mtn = (MT); if (mtn > MTILES - 1) mtn = MTILES - 1;                \
        if (lane == 0)                                                         \
            while (mt_done <= mtn) {                                           \
                if (ld_acq_(&g_ready[b * MTILES + mt_done]) >= 3u) mt_done++;  \
            }                                                                  \
    }

// Warp A chunk, shfl SOFTWARE-PIPELINED across steps:
//   prev0 consumed this step = carry (shfl issued LAST step, of new a2).
//   n2 (the only true per-step recurrence) computed FIRST; its shfl issued
//   immediately so the 26-cyc latency hides under n1/n0 and the next n2.
// Math identical to R12 (prev0(t) = alpha[l-1]@t-1 either way).
#define WA_CHUNK(LV, LVN, C, NST, PREFROWS)                                    \
    {                                                                          \
        int tb = 16 * (C) + 1;                                                 \
        _Pragma("unroll")                                                      \
        for (int i = 0; i < (NST); i++) {                                      \
            float prev0 = lane ? carry : NEG_INF2;                             \
            float n2 = lse2_(a2, a1,    LV[i*3+2]);                            \
            carry = __shfl_up_sync(0xffffffffu, n2, 1);                        \
            float n1 = lse2_(a1, a0,    LV[i*3+1]);                            \
            float n0 = lse2_(a0, prev0, LV[i*3+0]);                            \
            a0 = n0; a1 = n1; a2 = n2;                                         \
            int t = tb + i;                                                    \
            if (lane == 31) buf[(unsigned)(t >> 4) % 3u][t & 15] = a2;         \
            abp[0] = a0 * LN2_F; abp[1] = a1 * LN2_F; abp[2] = a2 * LN2_F;     \
            abp += LL;                                                         \
            if (t == mlb && lk >= 0) {                                         \
                float av = (lk == 0) ? a0 : ((lk == 1) ? a1 : a2);             \
                atomicAdd(loss, av * lossScale);                               \
            }                                                                  \
        }                                                                      \
        POLL_TILES((16 * (C) + 48) >> 6)                                       \
        if ((PREFROWS) > 0) {                                                  \
            const float* p = lpb + (size_t)(16 * ((C) + 1) + 1) * LL + lbase;  \
            _Pragma("unroll")                                                  \
            for (int i = 0; i < 16; i++) {                                     \
                const float* q = (i < (PREFROWS)) ? p : (p - LL);              \
                LVN[i*3+0] = q[0]; LVN[i*3+1] = q[1]; LVN[i*3+2] = q[2];       \
                p += LL;                                                       \
            }                                                                  \
        }                                                                      \
        SCAN_BAR();                                                            \
    }

#define WB_CHUNK(LV, LVN, C, NST, PREFROWS)                                    \
    {                                                                          \
        SCAN_BAR();                                                            \
        float bp[16];                                                          \
        _Pragma("unroll")                                                      \
        for (int i = 0; i < 16; i++) bp[i] = buf[(unsigned)(C) % 3u][i];       \
        int tb = 16 * (C) + 1;                                                 \
        _Pragma("unroll")                                                      \
        for (int i = 0; i < (NST); i++) {                                      \
            float prev0 = lane ? carry : bp[i];                                \
            float n1 = lse2_(a1, a0,    LV[i*2+1]);                            \
            carry = __shfl_up_sync(0xffffffffu, n1, 1);                        \
            float n0 = lse2_(a0, prev0, LV[i*2+0]);                            \
            a0 = n0; a1 = n1;                                                  \
            int t = tb + i;                                                    \
            abp[0] = a0 * LN2_F; abp[1] = a1 * LN2_F;                          \
            abp += LL;                                                         \
            if (t == mlb && lk >= 0) {                                         \
                float av = (lk == 0) ? a0 : a1;                                \
                atomicAdd(loss, av * lossScale);                               \
            }                                                                  \
        }                                                                      \
        if ((PREFROWS) > 0) {                                                  \
            const float* p = lpb + (size_t)(16 * ((C) + 1) + 1) * LL + lbase;  \
            _Pragma("unroll")                                                  \
            for (int i = 0; i < 16; i++) {                                     \
                const float* q = (i < (PREFROWS)) ? p : (p - LL);              \
                LVN[i*2+0] = q[0]; LVN[i*2+1] = q[1];                          \
                p += LL;                                                       \
            }                                                                  \
        }                                                                      \
    }

#define BK 16
__global__ void __launch_bounds__(256) fused_kernel(
    const float* __restrict__ mel,
    float* __restrict__ lp,
    float* __restrict__ alphas,
    const int* __restrict__ ml,
    const int* __restrict__ cl,
    float* __restrict__ loss)
{
    if (blockIdx.x < BB) {
        // ===================== SCAN (2-warp, shfl-pipelined) =================
        if (threadIdx.x >= 64) return;
        __shared__ float buf[3][16];

        int b = blockIdx.x;
        const float* lpb = lp + (size_t)b * TT * LL;
        float* ab = alphas + (size_t)b * TT * LL;
        int mlb = ml[b] - 1;
        int clb = cl[b] - 1;
        int w = threadIdx.x >> 5, lane = threadIdx.x & 31;
        const float lossScale = -(LN2_F / (float)BB);

        if (threadIdx.x == 0) buf[0][0] = NEG_INF2;

        // both warps: wait for tile (b,0) before ANY lp read
        if (lane == 0)
            while (ld_acq_(&g_ready[b * MTILES]) < 3u) {}
        __syncwarp();
        SCAN_BAR();   // buf seed visible, both warps released

        if (w == 0) {
            // -------- Warp A: l in [0,96), 3 per lane --------
            const int lbase = lane * 3;
            int lk = (clb < 96 && clb / 3 == lane) ? (clb % 3) : -1;
            int mt_done = 1;

            float a0 = NEG_INF2, a1 = NEG_INF2, a2 = NEG_INF2;
            if (lane == 0) a0 = lpb[0] * LOG2E_F;
            ab[lbase + 0] = a0 * LN2_F;
            ab[lbase + 1] = a1 * LN2_F;
            ab[lbase + 2] = a2 * LN2_F;

            float carry = __shfl_up_sync(0xffffffffu, a2, 1);  // alpha[l-1]@t=0

            float lvA[48], lvB[48];
            {
                const float* p = lpb + LL + lbase;
#pragma unroll
                for (int i = 0; i < 16; i++) {
                    lvA[i*3+0] = p[0]; lvA[i*3+1] = p[1]; lvA[i*3+2] = p[2];
                    p += LL;
                }
            }
            float* abp = ab + LL + lbase;

            for (int cc = 0; cc < 24; cc++) {
                int c0 = cc * 2;
                WA_CHUNK(lvA, lvB, c0,     16, 16)
                WA_CHUNK(lvB, lvA, c0 + 1, 16, 16)
            }
            WA_CHUNK(lvA, lvB, 48, 16, 15)
            WA_CHUNK(lvB, lvA, 49, 15, 0)
        } else {
            // -------- Warp B: l in [96,160), 2 per lane --------
            const int lbase = 96 + lane * 2;
            int lk = (clb >= 96 && (clb - 96) / 2 == lane) ? ((clb - 96) % 2) : -1;

            float a0 = NEG_INF2, a1 = NEG_INF2;
            ab[lbase + 0] = a0 * LN2_F;
            ab[lbase + 1] = a1 * LN2_F;

            float carry = __shfl_up_sync(0xffffffffu, a1, 1);  // alpha[l-1]@t=0

            float lvA[32], lvB[32];
            {
                const float* p = lpb + LL + lbase;
#pragma unroll
                for (int i = 0; i < 16; i++) {
                    lvA[i*2+0] = p[0]; lvA[i*2+1] = p[1];
                    p += LL;
                }
            }
            float* abp = ab + LL + lbase;

            for (int cc = 0; cc < 24; cc++) {
                int c0 = cc * 2;
                WB_CHUNK(lvA, lvB, c0,     16, 16)
                WB_CHUNK(lvB, lvA, c0 + 1, 16, 16)
            }
            WB_CHUNK(lvA, lvB, 48, 16, 15)
            WB_CHUNK(lvB, lvA, 49, 15, 0)
        }
        return;
    }

    // ========================= GEMM (unchanged) ===============================
    __shared__ float As [64][BK + 1];
    __shared__ float Bs1[BK][64];
    __shared__ float Bs2[BK][64];

    int gid = blockIdx.x - BB;
    int mt  = gid / (BB * 3);                 // m-tile: all batches first
    int rem = gid - mt * (BB * 3);
    int b   = rem / 3;
    int nt  = rem - b * 3;
    int m0  = mt * 64;
    int n0  = nt * 64;

    int tid = threadIdx.x;
    int tx = tid & 15, ty = tid >> 4;

    const float* melb = mel + (size_t)b * TT * DD;
    const float* Wb   = g_W + (size_t)b * KK2 * LL;
    float* lp_out = lp;

    int a_mm[4], a_kk[4], bl_kk[4], bl_nn[4];
    bool bl_ok[4];
    int a_t[4];
#pragma unroll
    for (int i = 0; i < 4; i++) {
        int lin = tid + i * 256;
        a_mm[i] = lin >> 4;  a_kk[i] = lin & 15;
        int t = m0 + a_mm[i]; if (t > TT - 1) t = TT - 1;
        a_t[i] = t;
        bl_kk[i] = lin >> 6; bl_nn[i] = lin & 63;
        bl_ok[i] = (n0 + bl_nn[i]) < LL;
    }

    float acc[4][4];
#pragma unroll
    for (int i = 0; i < 4; i++)
#pragma unroll
        for (int j = 0; j < 4; j++) acc[i][j] = 0.f;

#pragma unroll
    for (int i = 0; i < 4; i++) {
        As[a_mm[i]][a_kk[i]] = melb[(size_t)a_t[i] * DD + a_kk[i]];
        int l = n0 + bl_nn[i];
        Bs1[bl_kk[i]][bl_nn[i]] = bl_ok[i] ? Wb[(size_t)bl_kk[i] * LL + l] : 0.f;
        Bs2[bl_kk[i]][bl_nn[i]] = bl_ok[i] ? Wb[(size_t)(DD + bl_kk[i]) * LL + l] : 0.f;
    }
    __syncthreads();

    float ra[4], rb1[4], rb2[4];
    for (int it = 0; it < DD / BK; it++) {
        if (it < DD / BK - 1) {
            int k0 = (it + 1) * BK;
#pragma unroll
            for (int i = 0; i < 4; i++) {
                ra[i] = melb[(size_t)a_t[i] * DD + k0 + a_kk[i]];
                int l = n0 + bl_nn[i];
                rb1[i] = bl_ok[i] ? Wb[(size_t)(k0 + bl_kk[i]) * LL + l] : 0.f;
                rb2[i] = bl_ok[i] ? Wb[(size_t)(DD + k0 + bl_kk[i]) * LL + l] : 0.f;
            }
        }
#pragma unroll
        for (int kk = 0; kk < BK; kk++) {
            float a0 = As[ty * 4 + 0][kk];
            float a1 = As[ty * 4 + 1][kk];
            float a2 = As[ty * 4 + 2][kk];
            float a3 = As[ty * 4 + 3][kk];
            float q0 = a0 * a0, q1 = a1 * a1, q2 = a2 * a2, q3 = a3 * a3;
            float4 b1 = *(const float4*)&Bs1[kk][tx * 4];
            float4 b2 = *(const float4*)&Bs2[kk][tx * 4];
            acc[0][0] += q0 * b1.x; acc[0][1] += q0 * b1.y; acc[0][2] += q0 * b1.z; acc[0][3] += q0 * b1.w;
            acc[1][0] += q1 * b1.x; acc[1][1] += q1 * b1.y; acc[1][2] += q1 * b1.z; acc[1][3] += q1 * b1.w;
            acc[2][0] += q2 * b1.x; acc[2][1] += q2 * b1.y; acc[2][2] += q2 * b1.z; acc[2][3] += q2 * b1.w;
            acc[3][0] += q3 * b1.x; acc[3][1] += q3 * b1.y; acc[3][2] += q3 * b1.z; acc[3][3] += q3 * b1.w;
            acc[0][0] += a0 * b2.x; acc[0][1] += a0 * b2.y; acc[0][2] += a0 * b2.z; acc[0][3] += a0 * b2.w;
            acc[1][0] += a1 * b2.x; acc[1][1] += a1 * b2.y; acc[1][2] += a1 * b2.z; acc[1][3] += a1 * b2.w;
            acc[2][0] += a2 * b2.x; acc[2][1] += a2 * b2.y; acc[2][2] += a2 * b2.z; acc[2][3] += a2 * b2.w;
            acc[3][0] += a3 * b2.x; acc[3][1] += a3 * b2.y; acc[3][2] += a3 * b2.z; acc[3][3] += a3 * b2.w;
        }
        __syncthreads();
        if (it < DD / BK - 1) {
#pragma unroll
            for (int i = 0; i < 4; i++) {
                As[a_mm[i]][a_kk[i]]    = ra[i];
                Bs1[bl_kk[i]][bl_nn[i]] = rb1[i];
                Bs2[bl_kk[i]][bl_nn[i]] = rb2[i];
            }
            __syncthreads();
        }
    }

#pragma unroll
    for (int i = 0; i < 4; i++) {
        int t = m0 + ty * 4 + i;
        if (t >= TT) continue;
#pragma unroll
        for (int j = 0; j < 4; j++) {
            int l = n0 + tx * 4 + j;
            if (l < LL)
                lp_out[((size_t)b * TT + t) * LL + l] = acc[i][j] + g_C[b * LL + l];
        }
    }

    __threadfence();
    __syncthreads();
    if (tid == 0) atomicAdd(&g_ready[b * MTILES + mt], 1u);
}

// ---------------------------------------------------------------------------
extern "C" void kernel_launch(void* const* d_in, const int* in_sizes, int n_in,
                              void* d_out, int out_size) {
    const float* mel      = (const float*)d_in[0];
    const float* mu_sigma = (const float*)d_in[1];
    const int*   ml       = (const int*)d_in[2];
    const int*   cl       = (const int*)d_in[3];

    float* out    = (float*)d_out;
    float* lp     = out;                              // [B,T,L]
    float* loss   = out + (size_t)BB * TT * LL;       // [1]
    float* alphas = loss + 1;                         // [B,T,L]

    param_kernel<<<(BB * LL * 32 + 127) / 128, 128>>>(mu_sigma, loss);

    // 16 scan blocks + 16*13*3 = 624 gemm blocks
    fused_kernel<<<BB + BB * MTILES * 3, 256>>>(mel, lp, alphas, ml, cl, loss);
}

// round 15
// speedup vs baseline: 1.1910x; 1.1910x over previous
#include <cuda_runtime.h>
#include <math.h>

#define BB 16
#define TT 800
#define LL 160
#define DD 80
#define KK2 (2*DD)
#define HALF_LOG2PI 0.9189385332046727f
#define LOG2E_F 1.4426950408889634f
#define LN2_F   0.6931471805599453f
#define NEG_INF2 (-1.4426950408889634e20f)   // -1e20 in log2 units
#define MTILES 13                            // ceil(800/64)
#define GEMM_BLOCKS 132
#define TOTAL_TILES (MTILES * BB * 3)        // 624
#define FUSED_SMEM (132 * 1024)              // forces 1 block / SM

__device__ __align__(16) float g_W[BB * KK2 * LL];   // [b][k][l]
__device__ __align__(16) float g_C[BB * LL];
__device__ unsigned g_ready[BB * MTILES];            // 3 n-blocks arrive per tile

// ---------------------------------------------------------------------------
__device__ __forceinline__ float tanha_(float x) {
    float r; asm("tanh.approx.f32 %0, %1;" : "=f"(r) : "f"(x)); return r;
}
__device__ __forceinline__ float ex2f_(float x) {
    float r; asm("ex2.approx.ftz.f32 %0, %1;" : "=f"(r) : "f"(x)); return r;
}
__device__ __forceinline__ float lg2f_(float x) {
    float r; asm("lg2.approx.ftz.f32 %0, %1;" : "=f"(r) : "f"(x)); return r;
}
__device__ __forceinline__ unsigned ld_acq_(const unsigned* p) {
    unsigned v;
    asm volatile("ld.acquire.gpu.u32 %0, [%1];" : "=r"(v) : "l"(p));
    return v;
}

// ---------------------------------------------------------------------------
// K0: param transform + zero loss + zero readiness flags (unchanged).
// ---------------------------------------------------------------------------
__global__ void param_kernel(const float* __restrict__ mu_sigma,
                             float* __restrict__ loss) {
    if (blockIdx.x == 0) {
        if (threadIdx.x == 0) *loss = 0.f;
        if (threadIdx.x < BB * MTILES) g_ready[threadIdx.x] = 0u;
    }

    int wl   = (blockIdx.x * blockDim.x + threadIdx.x) >> 5;
    int lane = threadIdx.x & 31;
    if (wl >= BB * LL) return;
    int b = wl / LL, l = wl % LL;
    const float* ms = mu_sigma + (size_t)(b * LL + l) * KK2;

    float qmu = 0.f, sl = 0.f;
    for (int d = lane; d < DD; d += 32) {
        float mu = 2.f + 2.f * tanha_(0.5f * ms[d]);        // 4*sigmoid(x)
        float ls = 4.f * tanha_(ms[DD + d]);                // 4*tanh(x)
        float iv = ex2f_(-2.f * LOG2E_F * ls);              // exp(-2*ls)
        g_W[((size_t)b * KK2 + d)      * LL + l] = -0.5f * iv;
        g_W[((size_t)b * KK2 + DD + d) * LL + l] = mu * iv;
        qmu += mu * mu * iv;
        sl  += ls;
    }
#pragma unroll
    for (int o = 16; o; o >>= 1) {
        qmu += __shfl_xor_sync(0xffffffffu, qmu, o);
        sl  += __shfl_xor_sync(0xffffffffu, sl, o);
    }
    if (lane == 0)
        g_C[b * LL + l] = -0.5f * qmu - 0.5f * sl - (float)DD * HALF_LOG2PI;
}

// ---------------------------------------------------------------------------
__device__ __forceinline__ float lse2_(float a, float p, float lpv) {
    float m = fmaxf(a, p);
    float d = fminf(a, p) - m;             // <= 0
    float s = lg2f_(1.f + ex2f_(d));
    return fmaf(lpv, LOG2E_F, m) + s;
}

#define SCAN_BAR() asm volatile("bar.sync 1, 64;" ::: "memory")

// Poll (lane 0) until tiles 0..MT of batch b are ready; cumulative cursor.
#define POLL_TILES(MT)                                                         \
    {                                                                          \
        int mtn = (MT); if (mtn > MTILES - 1) mtn = MTILES - 1;                \
        if (lane == 0)                                                         \
            while (mt_done <= mtn) {                                           \
                if (ld_acq_(&g_ready[b * MTILES + mt_done]) >= 3u) mt_done++;  \
            }                                                                  \
    }

// R12-exact scan chunk macros (burst prefetch, natural shfl placement).
#define WA_CHUNK(LV, LVN, C, NST, PREFROWS)                                    \
    {                                                                          \
        int tb = 16 * (C) + 1;                                                 \
        _Pragma("unroll")                                                      \
        for (int i = 0; i < (NST); i++) {                                      \
            float top   = __shfl_up_sync(0xffffffffu, a2, 1);                  \
            float prev0 = lane ? top : NEG_INF2;                               \
            float n2 = lse2_(a2, a1,    LV[i*3+2]);                            \
            float n1 = lse2_(a1, a0,    LV[i*3+1]);                            \
            float n0 = lse2_(a0, prev0, LV[i*3+0]);                            \
            a0 = n0; a1 = n1; a2 = n2;                                         \
            int t = tb + i;                                                    \
            if (lane == 31) buf[((unsigned)(t >> 4) % 3u) * 16 + (t & 15)] = a2; \
            abp[0] = a0 * LN2_F; abp[1] = a1 * LN2_F; abp[2] = a2 * LN2_F;     \
            abp += LL;                                                         \
            if (t == mlb && lk >= 0) {                                         \
                float av = (lk == 0) ? a0 : ((lk == 1) ? a1 : a2);             \
                atomicAdd(loss, av * lossScale);                               \
            }                                                                  \
        }                                                                      \
        POLL_TILES((16 * (C) + 48) >> 6)                                       \
        if ((PREFROWS) > 0) {                                                  \
            const float* p = lpb + (size_t)(16 * ((C) + 1) + 1) * LL + lbase;  \
            _Pragma("unroll")                                                  \
            for (int i = 0; i < 16; i++) {                                     \
                const float* q = (i < (PREFROWS)) ? p : (p - LL);              \
                LVN[i*3+0] = q[0]; LVN[i*3+1] = q[1]; LVN[i*3+2] = q[2];       \
                p += LL;                                                       \
            }                                                                  \
        }                                                                      \
        SCAN_BAR();                                                            \
    }

#define WB_CHUNK(LV, LVN, C, NST, PREFROWS)                                    \
    {                                                                          \
        SCAN_BAR();                                                            \
        float bp[16];                                                          \
        _Pragma("unroll")                                                      \
        for (int i = 0; i < 16; i++) bp[i] = buf[((unsigned)(C) % 3u) * 16 + i]; \
        int tb = 16 * (C) + 1;                                                 \
        _Pragma("unroll")                                                      \
        for (int i = 0; i < (NST); i++) {                                      \
            float top   = __shfl_up_sync(0xffffffffu, a1, 1);                  \
            float prev0 = lane ? top : bp[i];                                  \
            float n1 = lse2_(a1, a0,    LV[i*2+1]);                            \
            float n0 = lse2_(a0, prev0, LV[i*2+0]);                            \
            a0 = n0; a1 = n1;                                                  \
            int t = tb + i;                                                    \
            abp[0] = a0 * LN2_F; abp[1] = a1 * LN2_F;                          \
            abp += LL;                                                         \
            if (t == mlb && lk >= 0) {                                         \
                float av = (lk == 0) ? a0 : a1;                                \
                atomicAdd(loss, av * lossScale);                               \
            }                                                                  \
        }                                                                      \
        if ((PREFROWS) > 0) {                                                  \
            const float* p = lpb + (size_t)(16 * ((C) + 1) + 1) * LL + lbase;  \
            _Pragma("unroll")                                                  \
            for (int i = 0; i < 16; i++) {                                     \
                const float* q = (i < (PREFROWS)) ? p : (p - LL);              \
                LVN[i*2+0] = q[0]; LVN[i*2+1] = q[1];                          \
                p += LL;                                                       \
            }                                                                  \
        }                                                                      \
    }

#define BK 16
__global__ void __launch_bounds__(256) fused_kernel(
    const float* __restrict__ mel,
    float* __restrict__ lp,
    float* __restrict__ alphas,
    const int* __restrict__ ml,
    const int* __restrict__ cl,
    float* __restrict__ loss)
{
    extern __shared__ char smem_raw[];

    if (blockIdx.x < BB) {
        // ===================== SCAN (R12-exact, dedicated SM) ================
        if (threadIdx.x >= 64) return;
        float* buf = (float*)smem_raw;   // [3][16] boundary buffer

        int b = blockIdx.x;
        const float* lpb = lp + (size_t)b * TT * LL;
        float* ab = alphas + (size_t)b * TT * LL;
        int mlb = ml[b] - 1;
        int clb = cl[b] - 1;
        int w = threadIdx.x >> 5, lane = threadIdx.x & 31;
        const float lossScale = -(LN2_F / (float)BB);

        if (threadIdx.x == 0) buf[0] = NEG_INF2;

        // both warps: wait for tile (b,0) before ANY lp read
        if (lane == 0)
            while (ld_acq_(&g_ready[b * MTILES]) < 3u) {}
        __syncwarp();
        SCAN_BAR();   // buf seed visible, both warps released

        if (w == 0) {
            // -------- Warp A: l in [0,96), 3 per lane --------
            const int lbase = lane * 3;
            int lk = (clb < 96 && clb / 3 == lane) ? (clb % 3) : -1;
            int mt_done = 1;

            float a0 = NEG_INF2, a1 = NEG_INF2, a2 = NEG_INF2;
            if (lane == 0) a0 = lpb[0] * LOG2E_F;
            ab[lbase + 0] = a0 * LN2_F;
            ab[lbase + 1] = a1 * LN2_F;
            ab[lbase + 2] = a2 * LN2_F;

            float lvA[48], lvB[48];
            {
                const float* p = lpb + LL + lbase;
#pragma unroll
                for (int i = 0; i < 16; i++) {
                    lvA[i*3+0] = p[0]; lvA[i*3+1] = p[1]; lvA[i*3+2] = p[2];
                    p += LL;
                }
            }
            float* abp = ab + LL + lbase;

            for (int cc = 0; cc < 24; cc++) {
                int c0 = cc * 2;
                WA_CHUNK(lvA, lvB, c0,     16, 16)
                WA_CHUNK(lvB, lvA, c0 + 1, 16, 16)
            }
            WA_CHUNK(lvA, lvB, 48, 16, 15)
            WA_CHUNK(lvB, lvA, 49, 15, 0)
        } else {
            // -------- Warp B: l in [96,160), 2 per lane --------
            const int lbase = 96 + lane * 2;
            int lk = (clb >= 96 && (clb - 96) / 2 == lane) ? ((clb - 96) % 2) : -1;

            float a0 = NEG_INF2, a1 = NEG_INF2;
            ab[lbase + 0] = a0 * LN2_F;
            ab[lbase + 1] = a1 * LN2_F;

            float lvA[32], lvB[32];
            {
                const float* p = lpb + LL + lbase;
#pragma unroll
                for (int i = 0; i < 16; i++) {
                    lvA[i*2+0] = p[0]; lvA[i*2+1] = p[1];
                    p += LL;
                }
            }
            float* abp = ab + LL + lbase;

            for (int cc = 0; cc < 24; cc++) {
                int c0 = cc * 2;
                WB_CHUNK(lvA, lvB, c0,     16, 16)
                WB_CHUNK(lvB, lvA, c0 + 1, 16, 16)
            }
            WB_CHUNK(lvA, lvB, 48, 16, 15)
            WB_CHUNK(lvB, lvA, 49, 15, 0)
        }
        return;
    }

    // ============== PERSISTENT GEMM: ~4.7 tiles per block, m-major ===========
    float (*As)[BK + 1] = (float(*)[BK + 1])smem_raw;                 // 64x17
    float (*Bs1)[64]    = (float(*)[64])(smem_raw + 64 * (BK + 1) * 4);
    float (*Bs2)[64]    = (float(*)[64])(smem_raw + 64 * (BK + 1) * 4 + BK * 64 * 4);

    int tid = threadIdx.x;
    int tx = tid & 15, ty = tid >> 4;

    for (int tile = (int)blockIdx.x - BB; tile < TOTAL_TILES; tile += GEMM_BLOCKS) {
        int mt  = tile / (BB * 3);                 // m-tile: all batches first
        int rem = tile - mt * (BB * 3);
        int b   = rem / 3;
        int nt  = rem - b * 3;
        int m0  = mt * 64;
        int n0  = nt * 64;

        const float* melb = mel + (size_t)b * TT * DD;
        const float* Wb   = g_W + (size_t)b * KK2 * LL;

        int a_mm[4], a_kk[4], bl_kk[4], bl_nn[4];
        bool bl_ok[4];
        int a_t[4];
#pragma unroll
        for (int i = 0; i < 4; i++) {
            int lin = tid + i * 256;
            a_mm[i] = lin >> 4;  a_kk[i] = lin & 15;
            int t = m0 + a_mm[i]; if (t > TT - 1) t = TT - 1;
            a_t[i] = t;
            bl_kk[i] = lin >> 6; bl_nn[i] = lin & 63;
            bl_ok[i] = (n0 + bl_nn[i]) < LL;
        }

        float acc[4][4];
#pragma unroll
        for (int i = 0; i < 4; i++)
#pragma unroll
            for (int j = 0; j < 4; j++) acc[i][j] = 0.f;

#pragma unroll
        for (int i = 0; i < 4; i++) {
            As[a_mm[i]][a_kk[i]] = melb[(size_t)a_t[i] * DD + a_kk[i]];
            int l = n0 + bl_nn[i];
            Bs1[bl_kk[i]][bl_nn[i]] = bl_ok[i] ? Wb[(size_t)bl_kk[i] * LL + l] : 0.f;
            Bs2[bl_kk[i]][bl_nn[i]] = bl_ok[i] ? Wb[(size_t)(DD + bl_kk[i]) * LL + l] : 0.f;
        }
        __syncthreads();

        float ra[4], rb1[4], rb2[4];
        for (int it = 0; it < DD / BK; it++) {
            if (it < DD / BK - 1) {
                int k0 = (it + 1) * BK;
#pragma unroll
                for (int i = 0; i < 4; i++) {
                    ra[i] = melb[(size_t)a_t[i] * DD + k0 + a_kk[i]];
                    int l = n0 + bl_nn[i];
                    rb1[i] = bl_ok[i] ? Wb[(size_t)(k0 + bl_kk[i]) * LL + l] : 0.f;
                    rb2[i] = bl_ok[i] ? Wb[(size_t)(DD + k0 + bl_kk[i]) * LL + l] : 0.f;
                }
            }
#pragma unroll
            for (int kk = 0; kk < BK; kk++) {
                float a0 = As[ty * 4 + 0][kk];
                float a1 = As[ty * 4 + 1][kk];
                float a2 = As[ty * 4 + 2][kk];
                float a3 = As[ty * 4 + 3][kk];
                float q0 = a0 * a0, q1 = a1 * a1, q2 = a2 * a2, q3 = a3 * a3;
                float4 b1 = *(const float4*)&Bs1[kk][tx * 4];
                float4 b2 = *(const float4*)&Bs2[kk][tx * 4];
                acc[0][0] += q0 * b1.x; acc[0][1] += q0 * b1.y; acc[0][2] += q0 * b1.z; acc[0][3] += q0 * b1.w;
                acc[1][0] += q1 * b1.x; acc[1][1] += q1 * b1.y; acc[1][2] += q1 * b1.z; acc[1][3] += q1 * b1.w;
                acc[2][0] += q2 * b1.x; acc[2][1] += q2 * b1.y; acc[2][2] += q2 * b1.z; acc[2][3] += q2 * b1.w;
                acc[3][0] += q3 * b1.x; acc[3][1] += q3 * b1.y; acc[3][2] += q3 * b1.z; acc[3][3] += q3 * b1.w;
                acc[0][0] += a0 * b2.x; acc[0][1] += a0 * b2.y; acc[0][2] += a0 * b2.z; acc[0][3] += a0 * b2.w;
                acc[1][0] += a1 * b2.x; acc[1][1] += a1 * b2.y; acc[1][2] += a1 * b2.z; acc[1][3] += a1 * b2.w;
                acc[2][0] += a2 * b2.x; acc[2][1] += a2 * b2.y; acc[2][2] += a2 * b2.z; acc[2][3] += a2 * b2.w;
                acc[3][0] += a3 * b2.x; acc[3][1] += a3 * b2.y; acc[3][2] += a3 * b2.z; acc[3][3] += a3 * b2.w;
            }
            __syncthreads();
            if (it < DD / BK - 1) {
#pragma unroll
                for (int i = 0; i < 4; i++) {
                    As[a_mm[i]][a_kk[i]]    = ra[i];
                    Bs1[bl_kk[i]][bl_nn[i]] = rb1[i];
                    Bs2[bl_kk[i]][bl_nn[i]] = rb2[i];
                }
                __syncthreads();
            }
        }

#pragma unroll
        for (int i = 0; i < 4; i++) {
            int t = m0 + ty * 4 + i;
            if (t >= TT) continue;
#pragma unroll
            for (int j = 0; j < 4; j++) {
                int l = n0 + tx * 4 + j;
                if (l < LL)
                    lp[((size_t)b * TT + t) * LL + l] = acc[i][j] + g_C[b * LL + l];
            }
        }

        // publish this (b, m-tile); syncthreads also isolates smem for next tile
        __threadfence();
        __syncthreads();
        if (tid == 0) atomicAdd(&g_ready[b * MTILES + mt], 1u);
    }
}

// ---------------------------------------------------------------------------
extern "C" void kernel_launch(void* const* d_in, const int* in_sizes, int n_in,
                              void* d_out, int out_size) {
    const float* mel      = (const float*)d_in[0];
    const float* mu_sigma = (const float*)d_in[1];
    const int*   ml       = (const int*)d_in[2];
    const int*   cl       = (const int*)d_in[3];

    float* out    = (float*)d_out;
    float* lp     = out;                              // [B,T,L]
    float* loss   = out + (size_t)BB * TT * LL;       // [1]
    float* alphas = loss + 1;                         // [B,T,L]

    param_kernel<<<(BB * LL * 32 + 127) / 128, 128>>>(mu_sigma, loss);

    cudaFuncSetAttribute(fused_kernel,
                         cudaFuncAttributeMaxDynamicSharedMemorySize, FUSED_SMEM);
    // 16 scan blocks + 132 persistent GEMM blocks = 148 = one block per SM
    fused_kernel<<<BB + GEMM_BLOCKS, 256, FUSED_SMEM>>>(mel, lp, alphas, ml, cl, loss);
}